// round 16
// baseline (speedup 1.0000x reference)
#include <cuda_runtime.h>
#include <cuda_fp16.h>
#include <cstdint>
#include <math.h>

#define NN 512
#define DD 128
#define NP (NN*NN)

__device__ __half g_a [(size_t)DD*NP];   // a, fp16, head-major [h][i*N+k]
__device__ __half g_b [(size_t)DD*NP];   // b, fp16, head-major [h][j*N+k]
__device__ __half g_x [(size_t)DD*NP];   // triangle result fp16, head-major
__device__ __half g_w [640*DD];          // virtual weight matrix fp16

// ---------------------------------------------------------------------------
__device__ __forceinline__ void mma16(float c[4], uint32_t a0, uint32_t a1,
                                      uint32_t a2, uint32_t a3,
                                      uint32_t b0, uint32_t b1){
    asm volatile(
        "mma.sync.aligned.m16n8k16.row.col.f32.f16.f16.f32 "
        "{%0,%1,%2,%3}, {%4,%5,%6,%7}, {%8,%9}, {%0,%1,%2,%3};"
        : "+f"(c[0]), "+f"(c[1]), "+f"(c[2]), "+f"(c[3])
        : "r"(a0), "r"(a1), "r"(a2), "r"(a3), "r"(b0), "r"(b1));
}
__device__ __forceinline__ uint32_t smem_u32(const void* p){
    uint32_t a;
    asm("{ .reg .u64 t; cvta.to.shared.u64 t, %1; cvt.u32.u64 %0, t; }" : "=r"(a) : "l"(p));
    return a;
}
__device__ __forceinline__ void cp16(uint32_t dst, const void* src){
    asm volatile("cp.async.cg.shared.global [%0], [%1], 16;" :: "r"(dst), "l"(src) : "memory");
}
#define CP_COMMIT() asm volatile("cp.async.commit_group;" ::: "memory")
#define CP_WAIT0()  asm volatile("cp.async.wait_group 0;" ::: "memory")
#define CP_WAIT1()  asm volatile("cp.async.wait_group 1;" ::: "memory")

// ---------------------------------------------------------------------------
// prep_w: fp16 virtual weight matrix. rows 0..127 = w_g ; 128+2t = w_ab_p[t] ;
// 129+2t = w_ab_g[t].
// ---------------------------------------------------------------------------
__global__ void prep_w(const float* __restrict__ wg,
                       const float* __restrict__ wap,
                       const float* __restrict__ wag){
    int idx = blockIdx.x*256 + threadIdx.x;      // 81920 total
    int row = idx >> 7, col = idx & 127;
    const float* src;
    if (row < 128) src = wg + row*DD;
    else { int t = (row-128)>>1; src = (row & 1) ? (wag + t*DD) : (wap + t*DD); }
    g_w[idx] = __float2half_rn(src[col]);
}

// ---------------------------------------------------------------------------
// proj: 128 pixels/CTA, fused LN. 20 W K-chunks via 6-slot ring, ONE barrier
// per 2 chunks (pair loop).
// smem (halves): A[128][136] | W 6x[128][40] | stage[64][136] = 113664 B (2 CTA/SM)
// ---------------------------------------------------------------------------
__global__ __launch_bounds__(256, 2)
void proj_kernel(const float* __restrict__ z,
                 const float* __restrict__ lnw, const float* __restrict__ lnb,
                 const float* __restrict__ mask,
                 const float* __restrict__ b_ab_p, const float* __restrict__ b_ab_g,
                 float* __restrict__ out_g) {
    extern __shared__ char shc[];
    __half* As    = (__half*)shc;            // [128][136]
    __half* Wb    = As + 128*136;            // 6 x [128][40]
    __half* stage = Wb + 6*128*40;           // [64][136]
    const int tid = threadIdx.x, warp = tid>>5, lane = tid&31;
    const int grp = lane>>2, qid = lane&3;
    const int wm = warp>>2, wn = warp&3;     // 2 x 4 warps
    const int mB = wm*64, nB = wn*32;
    const int pBase = blockIdx.x*128;
    uint32_t sW = smem_u32(Wb);

    // prefetch chunk pair 0 (chunks 0,1) and pair 1 (chunks 2,3)
    #pragma unroll
    for (int cc2 = 0; cc2 < 2; cc2++){
        #pragma unroll
        for (int t = 0; t < 2; t++){
            int idx = tid + t*256, r = idx >> 2, seg = idx & 3;
            cp16(sW + (uint32_t)(cc2*10240 + r*80 + seg*16),
                 g_w + (size_t)r*DD + cc2*32 + seg*8);
        }
    }
    CP_COMMIT();
    #pragma unroll
    for (int cc2 = 2; cc2 < 4; cc2++){
        #pragma unroll
        for (int t = 0; t < 2; t++){
            int idx = tid + t*256, r = idx >> 2, seg = idx & 3;
            cp16(sW + (uint32_t)(cc2*10240 + r*80 + seg*16),
                 g_w + (size_t)r*DD + cc2*32 + seg*8);
        }
    }
    CP_COMMIT();

    // hoisted mask values (nt-invariant), 4 m-tiles
    const float msc = 0.044194173824159216f;
    float mv0[4], mv1[4];
    #pragma unroll
    for (int mt = 0; mt < 4; mt++) {
        mv0[mt] = mask[pBase + mB + mt*16 + grp] * msc;
        mv1[mt] = mask[pBase + mB + mt*16 + grp + 8] * msc;
    }

    // fused input LayerNorm -> fp16 A tile, two 8-row-deep batches
    {
        float4 wv = ((const float4*)lnw)[lane];
        float4 bv = ((const float4*)lnb)[lane];
        #pragma unroll
        for (int hB = 0; hB < 2; hB++) {
            float4 vv[8];
            #pragma unroll
            for (int it = 0; it < 8; it++)
                vv[it] = ((const float4*)(z + (size_t)(pBase + hB*64 + it*8 + warp)*DD))[lane];
            float s[8], sq[8];
            #pragma unroll
            for (int it = 0; it < 8; it++) {
                float4 v = vv[it];
                s[it]  = v.x + v.y + v.z + v.w;
                sq[it] = v.x*v.x + v.y*v.y + v.z*v.z + v.w*v.w;
            }
            #pragma unroll
            for (int o = 16; o > 0; o >>= 1) {
                #pragma unroll
                for (int it = 0; it < 8; it++) {
                    s[it]  += __shfl_xor_sync(0xffffffffu, s[it],  o);
                    sq[it] += __shfl_xor_sync(0xffffffffu, sq[it], o);
                }
            }
            #pragma unroll
            for (int it = 0; it < 8; it++) {
                float mean = s[it] * (1.0f/128.0f);
                float var  = sq[it] * (1.0f/128.0f) - mean*mean;
                float rs   = rsqrtf(var + 1e-5f);
                float4 v = vv[it];
                __half* d = As + (hB*64 + it*8 + warp)*136 + lane*4;
                *(half2*)(d)     = __floats2half2_rn((v.x-mean)*rs*wv.x + bv.x,
                                                     (v.y-mean)*rs*wv.y + bv.y);
                *(half2*)(d + 2) = __floats2half2_rn((v.z-mean)*rs*wv.z + bv.z,
                                                     (v.w-mean)*rs*wv.w + bv.w);
            }
        }
    }

    float c[4][4][4];
    for (int g = 0; g < 10; g++) {                 // pair loop: chunks 2g, 2g+1
        if (g == 9) CP_WAIT0(); else CP_WAIT1();
        __syncthreads();
        if (g + 2 < 10) {
            #pragma unroll
            for (int s2 = 0; s2 < 2; s2++) {
                int cj = 2*g + 4 + s2;
                uint32_t dst = sW + (uint32_t)((cj % 6) * 10240);
                const __half* src = g_w + (size_t)(cj>>2)*128*DD + (cj&3)*32;
                #pragma unroll
                for (int t = 0; t < 2; t++){
                    int idx = tid + t*256, r = idx >> 2, seg = idx & 3;
                    cp16(dst + (uint32_t)(r*80 + seg*16), src + (size_t)r*DD + seg*8);
                }
            }
            CP_COMMIT();
        }
        #pragma unroll
        for (int sub = 0; sub < 2; sub++) {
            int ci = 2*g + sub;
            if ((ci & 3) == 0) {
                #pragma unroll
                for (int a = 0; a < 4; a++)
                    #pragma unroll
                    for (int b = 0; b < 4; b++)
                        #pragma unroll
                        for (int d = 0; d < 4; d++) c[a][b][d] = 0.f;
            }
            const __half* Ws = Wb + (ci % 6) * (128*40);
            #pragma unroll
            for (int kk = 0; kk < 2; kk++) {
                int k0w = kk*16 + 2*qid;
                int k0a = (ci&3)*32 + kk*16 + 2*qid;
                uint32_t bf[4][2];
                #pragma unroll
                for (int n2 = 0; n2 < 4; n2++) {
                    const __half* pb = Ws + (nB + n2*8 + grp)*40 + k0w;
                    bf[n2][0] = *(const uint32_t*)(pb);
                    bf[n2][1] = *(const uint32_t*)(pb + 8);
                }
                #pragma unroll
                for (int mt = 0; mt < 4; mt++) {
                    const __half* pa = As + (mB + mt*16 + grp)*136 + k0a;
                    uint32_t a0 = *(const uint32_t*)(pa);
                    uint32_t a1 = *(const uint32_t*)(pa + 8*136);
                    uint32_t a2 = *(const uint32_t*)(pa + 8);
                    uint32_t a3 = *(const uint32_t*)(pa + 8*136 + 8);
                    #pragma unroll
                    for (int n2 = 0; n2 < 4; n2++)
                        mma16(c[mt][n2], a0, a1, a2, a3, bf[n2][0], bf[n2][1]);
                }
            }
            if ((ci & 3) == 3) {
                int nt = ci >> 2;
                if (nt == 0) {
                    if (out_g != nullptr) {
                        #pragma unroll
                        for (int mt = 0; mt < 4; mt++) {
                            int p = pBase + mB + mt*16 + grp;
                            #pragma unroll
                            for (int n2 = 0; n2 < 4; n2++) {
                                int O = nB + n2*8 + 2*qid;
                                *(float2*)(out_g + (size_t)p*DD + O)     = make_float2(c[mt][n2][0], c[mt][n2][1]);
                                *(float2*)(out_g + (size_t)(p+8)*DD + O) = make_float2(c[mt][n2][2], c[mt][n2][3]);
                            }
                        }
                    }
                } else {
                    int tB = (nt-1)*64;
                    #pragma unroll
                    for (int mt = 0; mt < 4; mt++) {
                        int px = mB + mt*16 + grp;
                        #pragma unroll
                        for (int n2 = 0; n2 < 4; n2++) {
                            int tl = wn*16 + n2*4 + qid;
                            float bp = b_ab_p[tB + tl];
                            float bg = b_ab_g[tB + tl];
                            float v0 = (c[mt][n2][0] + bp) * mv0[mt] *
                                       (1.0f/(1.0f + __expf(-(c[mt][n2][1] + bg))));
                            float v1 = (c[mt][n2][2] + bp) * mv1[mt] *
                                       (1.0f/(1.0f + __expf(-(c[mt][n2][3] + bg))));
                            stage[tl*136 + px]     = __float2half_rn(v0);
                            stage[tl*136 + px + 8] = __float2half_rn(v1);
                        }
                    }
                    __syncthreads();
                    __half* dstM = (tB < 128) ? g_a : g_b;
                    int rowB = tB & 127;
                    #pragma unroll
                    for (int k = 0; k < 4; k++) {
                        int idx = tid + k*256, rr = idx >> 4, c8 = (idx & 15)*8;
                        *(float4*)(dstM + (size_t)(rowB + rr)*NP + pBase + c8) =
                            *(const float4*)(stage + rr*136 + c8);
                    }
                }
            }
        }
    }
}

// ---------------------------------------------------------------------------
// tri: X_h = A_h · B_h^T fp16, 128x128 C tile, K=512 in 16 chunks of 32,
// 3-stage ring, 1 barrier/chunk. (unchanged)
// smem: 3 x (A[128][40] + B[128][40]) halves = 61440 B
// ---------------------------------------------------------------------------
__global__ __launch_bounds__(256)
void tri_kernel() {
    extern __shared__ char shc[];
    __half* sh = (__half*)shc;
    const int tid = threadIdx.x, warp = tid>>5, lane = tid&31;
    const int grp = lane>>2, qid = lane&3;
    const int wm = warp>>2, wn = warp&3;
    const int mB = wm*64, nB = wn*32;
    int h  = blockIdx.y;
    int i0 = (blockIdx.x >> 2) * 128;
    int j0 = (blockIdx.x & 3) * 128;
    const __half* A = g_a + (size_t)h*NP + (size_t)i0*NN;
    const __half* B = g_b + (size_t)h*NP + (size_t)j0*NN;
    uint32_t s0 = smem_u32(sh);

    #pragma unroll
    for (int t = 0; t < 2; t++){
        int idx = tid + t*256, r = idx >> 2, seg = idx & 3;
        cp16(s0 + (uint32_t)(r*80 + seg*16),          A + (size_t)r*NN + seg*8);
        cp16(s0 + (uint32_t)(10240 + r*80 + seg*16),  B + (size_t)r*NN + seg*8);
    }
    CP_COMMIT();
    #pragma unroll
    for (int t = 0; t < 2; t++){
        int idx = tid + t*256, r = idx >> 2, seg = idx & 3;
        cp16(s0 + (uint32_t)(20480 + r*80 + seg*16),          A + (size_t)r*NN + 32 + seg*8);
        cp16(s0 + (uint32_t)(20480 + 10240 + r*80 + seg*16),  B + (size_t)r*NN + 32 + seg*8);
    }
    CP_COMMIT();

    float c[4][4][4];
    #pragma unroll
    for (int a = 0; a < 4; a++)
        #pragma unroll
        for (int b = 0; b < 4; b++)
            #pragma unroll
            for (int d = 0; d < 4; d++) c[a][b][d] = 0.f;

    for (int kc = 0; kc < 16; kc++) {
        if (kc == 15) CP_WAIT0(); else CP_WAIT1();
        __syncthreads();
        if (kc + 2 < 16) {
            int cj = kc + 2;
            uint32_t dst = s0 + (uint32_t)((cj % 3) * 20480);
            const __half* As_ = A + cj*32;
            const __half* Bs_ = B + cj*32;
            #pragma unroll
            for (int t = 0; t < 2; t++){
                int idx = tid + t*256, r = idx >> 2, seg = idx & 3;
                cp16(dst + (uint32_t)(r*80 + seg*16),         As_ + (size_t)r*NN + seg*8);
                cp16(dst + (uint32_t)(10240 + r*80 + seg*16), Bs_ + (size_t)r*NN + seg*8);
            }
            CP_COMMIT();
        }
        const __half* Asm = sh + (kc % 3) * 10240;
        const __half* Bsm = Asm + 5120;
        #pragma unroll
        for (int kk = 0; kk < 2; kk++) {
            int k0 = kk*16 + 2*qid;
            uint32_t bf[4][2];
            #pragma unroll
            for (int n2 = 0; n2 < 4; n2++) {
                const __half* pb = Bsm + (nB + n2*8 + grp)*40 + k0;
                bf[n2][0] = *(const uint32_t*)(pb);
                bf[n2][1] = *(const uint32_t*)(pb + 8);
            }
            #pragma unroll
            for (int mt = 0; mt < 4; mt++) {
                const __half* pa = Asm + (mB + mt*16 + grp)*40 + k0;
                uint32_t a0 = *(const uint32_t*)(pa);
                uint32_t a1 = *(const uint32_t*)(pa + 8*40);
                uint32_t a2 = *(const uint32_t*)(pa + 8);
                uint32_t a3 = *(const uint32_t*)(pa + 8*40 + 8);
                #pragma unroll
                for (int n2 = 0; n2 < 4; n2++)
                    mma16(c[mt][n2], a0, a1, a2, a3, bf[n2][0], bf[n2][1]);
            }
        }
    }
    __half* X = g_x + (size_t)h*NP;
    #pragma unroll
    for (int mt = 0; mt < 4; mt++) {
        int row = i0 + mB + mt*16 + grp;
        #pragma unroll
        for (int n2 = 0; n2 < 4; n2++) {
            int col = j0 + nB + n2*8 + 2*qid;
            *(half2*)(X + (size_t)row*NN + col)     = __floats2half2_rn(c[mt][n2][0], c[mt][n2][1]);
            *(half2*)(X + (size_t)(row+8)*NN + col) = __floats2half2_rn(c[mt][n2][2], c[mt][n2][3]);
        }
    }
}

// ---------------------------------------------------------------------------
// out: gather-transpose (half, MLP=16) + LN over H + barrier-free GEMM vs
// fully-preloaded w_z.  smem (halves): xt[128][136] + ws[128][136] = 69632 B
// ---------------------------------------------------------------------------
__global__ __launch_bounds__(256)
void out_kernel(const float* __restrict__ lnw,
                const float* __restrict__ lnb,
                const float* __restrict__ w_z,
                float* __restrict__ out_x) {
    extern __shared__ char shc[];
    __half* xt = (__half*)shc;       // [128 px][136]
    __half* ws = xt + 128*136;       // [128 d][136]  (full w_z, fp16)
    int tid = threadIdx.x, warp = tid >> 5, lane = tid & 31;
    int grp = lane >> 2, qid = lane & 3;
    int p0 = blockIdx.x * 128;

    // stage full w_z (fp16) — issued first for MLP, no barrier needed yet
    {
        int r = tid >> 1, half128 = (tid & 1) * 64;    // row d, col-half
        #pragma unroll
        for (int k = 0; k < 16; k++) {
            float4 v = *(const float4*)(w_z + r*DD + half128 + k*4);
            __half* pw = ws + r*136 + half128 + k*4;
            *(half2*)(pw)     = __floats2half2_rn(v.x, v.y);
            *(half2*)(pw + 2) = __floats2half2_rn(v.z, v.w);
        }
    }

    // gather transpose, 16 outstanding half loads per batch
    {
        int cpx = tid & 127, hh0 = tid >> 7;
        const __half* src = g_x + p0 + cpx;
        #pragma unroll
        for (int hb = 0; hb < 128; hb += 32) {
            __half tmp[16];
            #pragma unroll
            for (int k = 0; k < 16; k++)
                tmp[k] = src[(size_t)(hb + 2*k + hh0)*NP];
            #pragma unroll
            for (int k = 0; k < 16; k++)
                xt[cpx*136 + hb + 2*k + hh0] = tmp[k];
        }
    }
    __syncthreads();

    // LN over h in f32, 4 pixels per batch, write back fp16
    {
        float4 wv  = ((const float4*)lnw)[lane];
        float4 bvv = ((const float4*)lnb)[lane];
        #pragma unroll
        for (int pb = 0; pb < 16; pb += 4) {
            float2 f0[4], f1[4]; float s[4], sq[4];
            #pragma unroll
            for (int u = 0; u < 4; u++) {
                __half* p = xt + (warp*16 + pb + u)*136 + lane*4;
                f0[u] = __half22float2(*(half2*)(p));
                f1[u] = __half22float2(*(half2*)(p + 2));
                s[u]  = f0[u].x + f0[u].y + f1[u].x + f1[u].y;
                sq[u] = f0[u].x*f0[u].x + f0[u].y*f0[u].y + f1[u].x*f1[u].x + f1[u].y*f1[u].y;
            }
            #pragma unroll
            for (int o = 16; o > 0; o >>= 1) {
                #pragma unroll
                for (int u = 0; u < 4; u++) {
                    s[u]  += __shfl_xor_sync(0xffffffffu, s[u],  o);
                    sq[u] += __shfl_xor_sync(0xffffffffu, sq[u], o);
                }
            }
            #pragma unroll
            for (int u = 0; u < 4; u++) {
                float mean = s[u] * (1.0f/128.0f);
                float var  = sq[u] * (1.0f/128.0f) - mean*mean;
                float rs   = rsqrtf(var + 1e-5f);
                __half* p = xt + (warp*16 + pb + u)*136 + lane*4;
                *(half2*)(p)     = __floats2half2_rn((f0[u].x-mean)*rs*wv.x + bvv.x,
                                                     (f0[u].y-mean)*rs*wv.y + bvv.y);
                *(half2*)(p + 2) = __floats2half2_rn((f1[u].x-mean)*rs*wv.z + bvv.z,
                                                     (f1[u].y-mean)*rs*wv.w + bvv.w);
            }
        }
    }
    __syncthreads();

    int wm = warp >> 2, wn = warp & 3;
    int mB = wm*64, nB = wn*32;
    float c[4][4][4];
    #pragma unroll
    for (int a = 0; a < 4; a++)
        #pragma unroll
        for (int b = 0; b < 4; b++)
            #pragma unroll
            for (int d = 0; d < 4; d++) c[a][b][d] = 0.f;

    // barrier-free GEMM: ws and xt both fully resident
    #pragma unroll
    for (int kc = 0; kc < 4; kc++) {
        #pragma unroll
        for (int kk = 0; kk < 2; kk++) {
            int k0 = kc*32 + kk*16 + 2*qid;
            uint32_t bf[4][2];
            #pragma unroll
            for (int n2 = 0; n2 < 4; n2++) {
                const __half* pb = ws + (nB + n2*8 + grp)*136 + k0;
                bf[n2][0] = *(const uint32_t*)(pb);
                bf[n2][1] = *(const uint32_t*)(pb + 8);
            }
            #pragma unroll
            for (int mt = 0; mt < 4; mt++) {
                const __half* pa = xt + (mB + mt*16 + grp)*136 + k0;
                uint32_t a0 = *(const uint32_t*)(pa);
                uint32_t a1 = *(const uint32_t*)(pa + 8*136);
                uint32_t a2 = *(const uint32_t*)(pa + 8);
                uint32_t a3 = *(const uint32_t*)(pa + 8*136 + 8);
                #pragma unroll
                for (int n2 = 0; n2 < 4; n2++)
                    mma16(c[mt][n2], a0, a1, a2, a3, bf[n2][0], bf[n2][1]);
            }
        }
    }
    #pragma unroll
    for (int mt = 0; mt < 4; mt++) {
        int p = p0 + mB + mt*16 + grp;
        #pragma unroll
        for (int n2 = 0; n2 < 4; n2++) {
            int d = nB + n2*8 + 2*qid;
            *(float2*)(out_x + (size_t)p*DD + d)     = make_float2(c[mt][n2][0], c[mt][n2][1]);
            *(float2*)(out_x + (size_t)(p+8)*DD + d) = make_float2(c[mt][n2][2], c[mt][n2][3]);
        }
    }
}

// ---------------------------------------------------------------------------
extern "C" void kernel_launch(void* const* d_in, const int* in_sizes, int n_in,
                              void* d_out, int out_size) {
    const float* z       = (const float*)d_in[0];
    const float* mask    = (const float*)d_in[1];
    const float* ln_in_w = (const float*)d_in[2];
    const float* ln_in_b = (const float*)d_in[3];
    const float* w_ab_p  = (const float*)d_in[4];
    const float* b_ab_p  = (const float*)d_in[5];
    const float* w_ab_g  = (const float*)d_in[6];
    const float* b_ab_g  = (const float*)d_in[7];
    const float* w_g     = (const float*)d_in[8];
    const float* ln_out_w= (const float*)d_in[9];
    const float* ln_out_b= (const float*)d_in[10];
    const float* w_z     = (const float*)d_in[11];

    float* out_x = (float*)d_out;
    float* out_g = (out_size >= 2*NP*DD) ? (out_x + (size_t)NP*DD) : nullptr;

    const int projSmem = (128*136 + 6*128*40 + 64*136) * 2;  // 113664
    const int triSmem  = 3 * 2 * 128*40 * 2;                 // 61440
    const int outSmem  = (128*136 + 128*136) * 2;            // 69632
    cudaFuncSetAttribute(proj_kernel, cudaFuncAttributeMaxDynamicSharedMemorySize, projSmem);
    cudaFuncSetAttribute(tri_kernel,  cudaFuncAttributeMaxDynamicSharedMemorySize, triSmem);
    cudaFuncSetAttribute(out_kernel,  cudaFuncAttributeMaxDynamicSharedMemorySize, outSmem);

    prep_w<<<320, 256>>>(w_g, w_ab_p, w_ab_g);
    proj_kernel<<<NP/128, 256, projSmem>>>(z, ln_in_w, ln_in_b, mask, b_ab_p, b_ab_g, out_g);
    tri_kernel<<<dim3(16, 128), 256, triSmem>>>();
    out_kernel<<<NP/128, 256, outSmem>>>(ln_out_w, ln_out_b, w_z, out_x);
}

// round 17
// speedup vs baseline: 1.0968x; 1.0968x over previous
#include <cuda_runtime.h>
#include <cuda_fp16.h>
#include <cstdint>
#include <math.h>

#define NN 512
#define DD 128
#define NP (NN*NN)

__device__ __half g_a [(size_t)DD*NP];   // a, fp16, head-major [h][i*N+k]
__device__ __half g_b [(size_t)DD*NP];   // b, fp16, head-major [h][j*N+k]
__device__ __half g_x [(size_t)DD*NP];   // triangle result fp16, head-major
__device__ __half g_w [640*DD];          // virtual weight matrix fp16

// ---------------------------------------------------------------------------
__device__ __forceinline__ void mma16(float c[4], uint32_t a0, uint32_t a1,
                                      uint32_t a2, uint32_t a3,
                                      uint32_t b0, uint32_t b1){
    asm volatile(
        "mma.sync.aligned.m16n8k16.row.col.f32.f16.f16.f32 "
        "{%0,%1,%2,%3}, {%4,%5,%6,%7}, {%8,%9}, {%0,%1,%2,%3};"
        : "+f"(c[0]), "+f"(c[1]), "+f"(c[2]), "+f"(c[3])
        : "r"(a0), "r"(a1), "r"(a2), "r"(a3), "r"(b0), "r"(b1));
}
__device__ __forceinline__ uint32_t smem_u32(const void* p){
    uint32_t a;
    asm("{ .reg .u64 t; cvta.to.shared.u64 t, %1; cvt.u32.u64 %0, t; }" : "=r"(a) : "l"(p));
    return a;
}
__device__ __forceinline__ void cp16(uint32_t dst, const void* src){
    asm volatile("cp.async.cg.shared.global [%0], [%1], 16;" :: "r"(dst), "l"(src) : "memory");
}
#define CP_COMMIT() asm volatile("cp.async.commit_group;" ::: "memory")
#define CP_WAIT0()  asm volatile("cp.async.wait_group 0;" ::: "memory")
#define CP_WAIT1()  asm volatile("cp.async.wait_group 1;" ::: "memory")

// ---------------------------------------------------------------------------
// prep_w: fp16 virtual weight matrix. rows 0..127 = w_g ; 128+2t = w_ab_p[t] ;
// 129+2t = w_ab_g[t].
// ---------------------------------------------------------------------------
__global__ void prep_w(const float* __restrict__ wg,
                       const float* __restrict__ wap,
                       const float* __restrict__ wag){
    int idx = blockIdx.x*256 + threadIdx.x;      // 81920 total
    int row = idx >> 7, col = idx & 127;
    const float* src;
    if (row < 128) src = wg + row*DD;
    else { int t = (row-128)>>1; src = (row & 1) ? (wag + t*DD) : (wap + t*DD); }
    g_w[idx] = __float2half_rn(src[col]);
}

// ---------------------------------------------------------------------------
// proj: 128 pixels/CTA, fused LN, 20 W K-chunks (fp16) via 3-stage ring.
// smem (halves): A[128][136] | W 3x[128][40] | stage[64][136] = 82944 B (2 CTA/SM)
// ---------------------------------------------------------------------------
__global__ __launch_bounds__(256, 2)
void proj_kernel(const float* __restrict__ z,
                 const float* __restrict__ lnw, const float* __restrict__ lnb,
                 const float* __restrict__ mask,
                 const float* __restrict__ b_ab_p, const float* __restrict__ b_ab_g,
                 float* __restrict__ out_g) {
    extern __shared__ char shc[];
    __half* As    = (__half*)shc;            // [128][136]
    __half* Wb    = As + 128*136;            // 3 x [128][40]
    __half* stage = Wb + 3*128*40;           // [64][136]
    const int tid = threadIdx.x, warp = tid>>5, lane = tid&31;
    const int grp = lane>>2, qid = lane&3;
    const int wm = warp>>2, wn = warp&3;     // 2 x 4 warps
    const int mB = wm*64, nB = wn*32;
    const int pBase = blockIdx.x*128;
    uint32_t sW = smem_u32(Wb);

    // prefetch W chunks 0,1 : each 128 rows x 32 halves (64B/row)
    #pragma unroll
    for (int t = 0; t < 2; t++){
        int idx = tid + t*256, r = idx >> 2, seg = idx & 3;
        cp16(sW + (uint32_t)(r*80 + seg*16), g_w + (size_t)r*DD + seg*8);
    }
    CP_COMMIT();
    #pragma unroll
    for (int t = 0; t < 2; t++){
        int idx = tid + t*256, r = idx >> 2, seg = idx & 3;
        cp16(sW + (uint32_t)(10240 + r*80 + seg*16), g_w + (size_t)r*DD + 32 + seg*8);
    }
    CP_COMMIT();

    // hoisted mask values (nt-invariant), 4 m-tiles
    const float msc = 0.044194173824159216f;
    float mv0[4], mv1[4];
    #pragma unroll
    for (int mt = 0; mt < 4; mt++) {
        mv0[mt] = mask[pBase + mB + mt*16 + grp] * msc;
        mv1[mt] = mask[pBase + mB + mt*16 + grp + 8] * msc;
    }

    // fused input LayerNorm -> fp16 A tile, two 8-row-deep batches
    {
        float4 wv = ((const float4*)lnw)[lane];
        float4 bv = ((const float4*)lnb)[lane];
        #pragma unroll
        for (int hB = 0; hB < 2; hB++) {
            float4 vv[8];
            #pragma unroll
            for (int it = 0; it < 8; it++)
                vv[it] = ((const float4*)(z + (size_t)(pBase + hB*64 + it*8 + warp)*DD))[lane];
            float s[8], sq[8];
            #pragma unroll
            for (int it = 0; it < 8; it++) {
                float4 v = vv[it];
                s[it]  = v.x + v.y + v.z + v.w;
                sq[it] = v.x*v.x + v.y*v.y + v.z*v.z + v.w*v.w;
            }
            #pragma unroll
            for (int o = 16; o > 0; o >>= 1) {
                #pragma unroll
                for (int it = 0; it < 8; it++) {
                    s[it]  += __shfl_xor_sync(0xffffffffu, s[it],  o);
                    sq[it] += __shfl_xor_sync(0xffffffffu, sq[it], o);
                }
            }
            #pragma unroll
            for (int it = 0; it < 8; it++) {
                float mean = s[it] * (1.0f/128.0f);
                float var  = sq[it] * (1.0f/128.0f) - mean*mean;
                float rs   = rsqrtf(var + 1e-5f);
                float4 v = vv[it];
                __half* d = As + (hB*64 + it*8 + warp)*136 + lane*4;
                *(half2*)(d)     = __floats2half2_rn((v.x-mean)*rs*wv.x + bv.x,
                                                     (v.y-mean)*rs*wv.y + bv.y);
                *(half2*)(d + 2) = __floats2half2_rn((v.z-mean)*rs*wv.z + bv.z,
                                                     (v.w-mean)*rs*wv.w + bv.w);
            }
        }
    }

    float c[4][4][4];
    for (int ci = 0; ci < 20; ci++) {
        if ((ci & 3) == 0) {
            #pragma unroll
            for (int a = 0; a < 4; a++)
                #pragma unroll
                for (int b = 0; b < 4; b++)
                    #pragma unroll
                    for (int d = 0; d < 4; d++) c[a][b][d] = 0.f;
        }
        if (ci == 19) CP_WAIT0(); else CP_WAIT1();
        __syncthreads();
        if (ci + 2 < 20) {
            int cj = ci + 2;
            uint32_t dst = sW + (uint32_t)((cj % 3) * 10240);
            const __half* src = g_w + (size_t)(cj>>2)*128*DD + (cj&3)*32;
            #pragma unroll
            for (int t = 0; t < 2; t++){
                int idx = tid + t*256, r = idx >> 2, seg = idx & 3;
                cp16(dst + (uint32_t)(r*80 + seg*16), src + (size_t)r*DD + seg*8);
            }
            CP_COMMIT();
        }
        const __half* Ws = Wb + (ci % 3) * 128*40;
        #pragma unroll
        for (int kk = 0; kk < 2; kk++) {
            int k0w = kk*16 + 2*qid;
            int k0a = (ci&3)*32 + kk*16 + 2*qid;
            uint32_t bf[4][2];
            #pragma unroll
            for (int n2 = 0; n2 < 4; n2++) {
                const __half* pb = Ws + (nB + n2*8 + grp)*40 + k0w;
                bf[n2][0] = *(const uint32_t*)(pb);
                bf[n2][1] = *(const uint32_t*)(pb + 8);
            }
            #pragma unroll
            for (int mt = 0; mt < 4; mt++) {
                const __half* pa = As + (mB + mt*16 + grp)*136 + k0a;
                uint32_t a0 = *(const uint32_t*)(pa);
                uint32_t a1 = *(const uint32_t*)(pa + 8*136);
                uint32_t a2 = *(const uint32_t*)(pa + 8);
                uint32_t a3 = *(const uint32_t*)(pa + 8*136 + 8);
                #pragma unroll
                for (int n2 = 0; n2 < 4; n2++)
                    mma16(c[mt][n2], a0, a1, a2, a3, bf[n2][0], bf[n2][1]);
            }
        }
        if ((ci & 3) == 3) {
            int nt = ci >> 2;
            if (nt == 0) {
                if (out_g != nullptr) {
                    #pragma unroll
                    for (int mt = 0; mt < 4; mt++) {
                        int p = pBase + mB + mt*16 + grp;
                        #pragma unroll
                        for (int n2 = 0; n2 < 4; n2++) {
                            int O = nB + n2*8 + 2*qid;
                            *(float2*)(out_g + (size_t)p*DD + O)     = make_float2(c[mt][n2][0], c[mt][n2][1]);
                            *(float2*)(out_g + (size_t)(p+8)*DD + O) = make_float2(c[mt][n2][2], c[mt][n2][3]);
                        }
                    }
                }
            } else {
                int tB = (nt-1)*64;
                #pragma unroll
                for (int mt = 0; mt < 4; mt++) {
                    int px = mB + mt*16 + grp;
                    #pragma unroll
                    for (int n2 = 0; n2 < 4; n2++) {
                        int tl = wn*16 + n2*4 + qid;
                        float bp = b_ab_p[tB + tl];
                        float bg = b_ab_g[tB + tl];
                        float v0 = (c[mt][n2][0] + bp) * mv0[mt] *
                                   (1.0f/(1.0f + __expf(-(c[mt][n2][1] + bg))));
                        float v1 = (c[mt][n2][2] + bp) * mv1[mt] *
                                   (1.0f/(1.0f + __expf(-(c[mt][n2][3] + bg))));
                        stage[tl*136 + px]     = __float2half_rn(v0);
                        stage[tl*136 + px + 8] = __float2half_rn(v1);
                    }
                }
                __syncthreads();
                __half* dstM = (tB < 128) ? g_a : g_b;
                int rowB = tB & 127;
                #pragma unroll
                for (int k = 0; k < 4; k++) {
                    int idx = tid + k*256, rr = idx >> 4, c8 = (idx & 15)*8;
                    *(float4*)(dstM + (size_t)(rowB + rr)*NP + pBase + c8) =
                        *(const float4*)(stage + rr*136 + c8);
                }
            }
        }
    }
}

// ---------------------------------------------------------------------------
// tri: X_h = A_h · B_h^T fp16, 128x128 C tile, K=512 in 16 chunks of 32,
// 3-stage ring, 1 barrier/chunk.
// smem: 3 x (A[128][40] + B[128][40]) halves = 61440 B
// ---------------------------------------------------------------------------
__global__ __launch_bounds__(256)
void tri_kernel() {
    extern __shared__ char shc[];
    __half* sh = (__half*)shc;
    const int tid = threadIdx.x, warp = tid>>5, lane = tid&31;
    const int grp = lane>>2, qid = lane&3;
    const int wm = warp>>2, wn = warp&3;
    const int mB = wm*64, nB = wn*32;
    int h  = blockIdx.y;
    int i0 = (blockIdx.x >> 2) * 128;
    int j0 = (blockIdx.x & 3) * 128;
    const __half* A = g_a + (size_t)h*NP + (size_t)i0*NN;
    const __half* B = g_b + (size_t)h*NP + (size_t)j0*NN;
    uint32_t s0 = smem_u32(sh);

    #pragma unroll
    for (int t = 0; t < 2; t++){
        int idx = tid + t*256, r = idx >> 2, seg = idx & 3;
        cp16(s0 + (uint32_t)(r*80 + seg*16),          A + (size_t)r*NN + seg*8);
        cp16(s0 + (uint32_t)(10240 + r*80 + seg*16),  B + (size_t)r*NN + seg*8);
    }
    CP_COMMIT();
    #pragma unroll
    for (int t = 0; t < 2; t++){
        int idx = tid + t*256, r = idx >> 2, seg = idx & 3;
        cp16(s0 + (uint32_t)(20480 + r*80 + seg*16),          A + (size_t)r*NN + 32 + seg*8);
        cp16(s0 + (uint32_t)(20480 + 10240 + r*80 + seg*16),  B + (size_t)r*NN + 32 + seg*8);
    }
    CP_COMMIT();

    float c[4][4][4];
    #pragma unroll
    for (int a = 0; a < 4; a++)
        #pragma unroll
        for (int b = 0; b < 4; b++)
            #pragma unroll
            for (int d = 0; d < 4; d++) c[a][b][d] = 0.f;

    for (int kc = 0; kc < 16; kc++) {
        if (kc == 15) CP_WAIT0(); else CP_WAIT1();
        __syncthreads();
        if (kc + 2 < 16) {
            int cj = kc + 2;
            uint32_t dst = s0 + (uint32_t)((cj % 3) * 20480);
            const __half* As_ = A + cj*32;
            const __half* Bs_ = B + cj*32;
            #pragma unroll
            for (int t = 0; t < 2; t++){
                int idx = tid + t*256, r = idx >> 2, seg = idx & 3;
                cp16(dst + (uint32_t)(r*80 + seg*16),         As_ + (size_t)r*NN + seg*8);
                cp16(dst + (uint32_t)(10240 + r*80 + seg*16), Bs_ + (size_t)r*NN + seg*8);
            }
            CP_COMMIT();
        }
        const __half* Asm = sh + (kc % 3) * 10240;
        const __half* Bsm = Asm + 5120;
        #pragma unroll
        for (int kk = 0; kk < 2; kk++) {
            int k0 = kk*16 + 2*qid;
            uint32_t bf[4][2];
            #pragma unroll
            for (int n2 = 0; n2 < 4; n2++) {
                const __half* pb = Bsm + (nB + n2*8 + grp)*40 + k0;
                bf[n2][0] = *(const uint32_t*)(pb);
                bf[n2][1] = *(const uint32_t*)(pb + 8);
            }
            #pragma unroll
            for (int mt = 0; mt < 4; mt++) {
                const __half* pa = Asm + (mB + mt*16 + grp)*40 + k0;
                uint32_t a0 = *(const uint32_t*)(pa);
                uint32_t a1 = *(const uint32_t*)(pa + 8*40);
                uint32_t a2 = *(const uint32_t*)(pa + 8);
                uint32_t a3 = *(const uint32_t*)(pa + 8*40 + 8);
                #pragma unroll
                for (int n2 = 0; n2 < 4; n2++)
                    mma16(c[mt][n2], a0, a1, a2, a3, bf[n2][0], bf[n2][1]);
            }
        }
    }
    __half* X = g_x + (size_t)h*NP;
    #pragma unroll
    for (int mt = 0; mt < 4; mt++) {
        int row = i0 + mB + mt*16 + grp;
        #pragma unroll
        for (int n2 = 0; n2 < 4; n2++) {
            int col = j0 + nB + n2*8 + 2*qid;
            *(half2*)(X + (size_t)row*NN + col)     = __floats2half2_rn(c[mt][n2][0], c[mt][n2][1]);
            *(half2*)(X + (size_t)(row+8)*NN + col) = __floats2half2_rn(c[mt][n2][2], c[mt][n2][3]);
        }
    }
}

// ---------------------------------------------------------------------------
// out: gather-transpose (STS.128, conflict-light) + LN over H + GEMM vs w_z.
// smem (halves): xt[128][136] + ws[128][40] = 45056 B  (2 CTA/SM, regs<=128)
// ---------------------------------------------------------------------------
__global__ __launch_bounds__(256, 2)
void out_kernel(const float* __restrict__ lnw,
                const float* __restrict__ lnb,
                const float* __restrict__ w_z,
                float* __restrict__ out_x) {
    extern __shared__ char shc[];
    __half* xt = (__half*)shc;       // [128 px][136]
    __half* ws = xt + 128*136;       // [128 d][40]
    int tid = threadIdx.x, warp = tid >> 5, lane = tid & 31;
    int grp = lane >> 2, qid = lane & 3;
    int p0 = blockIdx.x * 128;

    // gather transpose: each thread gathers 8 consecutive h for ONE pixel,
    // packs, and writes one STS.128 (replaces 8-way-conflicted scalar STS).
    {
        int px = tid & 127, hq = tid >> 7;       // hq 0/1
        const __half* src = g_x + p0 + px;
        #pragma unroll
        for (int hb = 0; hb < 8; hb++) {
            int h0 = hb*16 + hq*8;
            __half tmp[8];
            #pragma unroll
            for (int k = 0; k < 8; k++)
                tmp[k] = src[(size_t)(h0 + k)*NP];
            *(float4*)(xt + px*136 + h0) = *(const float4*)tmp;
        }
    }
    __syncthreads();

    // LN over h in f32, 4 pixels per batch, write back fp16
    {
        float4 wv  = ((const float4*)lnw)[lane];
        float4 bvv = ((const float4*)lnb)[lane];
        #pragma unroll
        for (int pb = 0; pb < 16; pb += 4) {
            float2 f0[4], f1[4]; float s[4], sq[4];
            #pragma unroll
            for (int u = 0; u < 4; u++) {
                __half* p = xt + (warp*16 + pb + u)*136 + lane*4;
                f0[u] = __half22float2(*(half2*)(p));
                f1[u] = __half22float2(*(half2*)(p + 2));
                s[u]  = f0[u].x + f0[u].y + f1[u].x + f1[u].y;
                sq[u] = f0[u].x*f0[u].x + f0[u].y*f0[u].y + f1[u].x*f1[u].x + f1[u].y*f1[u].y;
            }
            #pragma unroll
            for (int o = 16; o > 0; o >>= 1) {
                #pragma unroll
                for (int u = 0; u < 4; u++) {
                    s[u]  += __shfl_xor_sync(0xffffffffu, s[u],  o);
                    sq[u] += __shfl_xor_sync(0xffffffffu, sq[u], o);
                }
            }
            #pragma unroll
            for (int u = 0; u < 4; u++) {
                float mean = s[u] * (1.0f/128.0f);
                float var  = sq[u] * (1.0f/128.0f) - mean*mean;
                float rs   = rsqrtf(var + 1e-5f);
                __half* p = xt + (warp*16 + pb + u)*136 + lane*4;
                *(half2*)(p)     = __floats2half2_rn((f0[u].x-mean)*rs*wv.x + bvv.x,
                                                     (f0[u].y-mean)*rs*wv.y + bvv.y);
                *(half2*)(p + 2) = __floats2half2_rn((f1[u].x-mean)*rs*wv.z + bvv.z,
                                                     (f1[u].y-mean)*rs*wv.w + bvv.w);
            }
        }
    }
    __syncthreads();

    int wm = warp >> 2, wn = warp & 3;
    int mB = wm*64, nB = wn*32;
    float c[4][4][4];
    #pragma unroll
    for (int a = 0; a < 4; a++)
        #pragma unroll
        for (int b = 0; b < 4; b++)
            #pragma unroll
            for (int d = 0; d < 4; d++) c[a][b][d] = 0.f;

    int r = tid >> 3, cc = (tid & 7) << 2;
    float4 wreg[4];
    #pragma unroll
    for (int k = 0; k < 4; k++)
        wreg[k] = *(const float4*)(w_z + (r + k*32)*DD + cc);

    for (int kc = 0; kc < 4; kc++) {
        #pragma unroll
        for (int k = 0; k < 4; k++) {
            float4 v = wreg[k];
            __half* pw = ws + (r + k*32)*40 + cc;
            *(half2*)(pw)     = __floats2half2_rn(v.x, v.y);
            *(half2*)(pw + 2) = __floats2half2_rn(v.z, v.w);
        }
        __syncthreads();
        if (kc + 1 < 4) {
            #pragma unroll
            for (int k = 0; k < 4; k++)
                wreg[k] = *(const float4*)(w_z + (r + k*32)*DD + (kc+1)*32 + cc);
        }
        #pragma unroll
        for (int kk = 0; kk < 2; kk++) {
            int k0w = kk*16 + 2*qid;
            int k0a = kc*32 + kk*16 + 2*qid;
            uint32_t bf[4][2];
            #pragma unroll
            for (int n2 = 0; n2 < 4; n2++) {
                const __half* pb = ws + (nB + n2*8 + grp)*40 + k0w;
                bf[n2][0] = *(const uint32_t*)(pb);
                bf[n2][1] = *(const uint32_t*)(pb + 8);
            }
            #pragma unroll
            for (int mt = 0; mt < 4; mt++) {
                const __half* pa = xt + (mB + mt*16 + grp)*136 + k0a;
                uint32_t a0 = *(const uint32_t*)(pa);
                uint32_t a1 = *(const uint32_t*)(pa + 8*136);
                uint32_t a2 = *(const uint32_t*)(pa + 8);
                uint32_t a3 = *(const uint32_t*)(pa + 8*136 + 8);
                #pragma unroll
                for (int n2 = 0; n2 < 4; n2++)
                    mma16(c[mt][n2], a0, a1, a2, a3, bf[n2][0], bf[n2][1]);
            }
        }
        __syncthreads();
    }
    #pragma unroll
    for (int mt = 0; mt < 4; mt++) {
        int p = p0 + mB + mt*16 + grp;
        #pragma unroll
        for (int n2 = 0; n2 < 4; n2++) {
            int d = nB + n2*8 + 2*qid;
            *(float2*)(out_x + (size_t)p*DD + d)     = make_float2(c[mt][n2][0], c[mt][n2][1]);
            *(float2*)(out_x + (size_t)(p+8)*DD + d) = make_float2(c[mt][n2][2], c[mt][n2][3]);
        }
    }
}

// ---------------------------------------------------------------------------
extern "C" void kernel_launch(void* const* d_in, const int* in_sizes, int n_in,
                              void* d_out, int out_size) {
    const float* z       = (const float*)d_in[0];
    const float* mask    = (const float*)d_in[1];
    const float* ln_in_w = (const float*)d_in[2];
    const float* ln_in_b = (const float*)d_in[3];
    const float* w_ab_p  = (const float*)d_in[4];
    const float* b_ab_p  = (const float*)d_in[5];
    const float* w_ab_g  = (const float*)d_in[6];
    const float* b_ab_g  = (const float*)d_in[7];
    const float* w_g     = (const float*)d_in[8];
    const float* ln_out_w= (const float*)d_in[9];
    const float* ln_out_b= (const float*)d_in[10];
    const float* w_z     = (const float*)d_in[11];

    float* out_x = (float*)d_out;
    float* out_g = (out_size >= 2*NP*DD) ? (out_x + (size_t)NP*DD) : nullptr;

    const int projSmem = (128*136 + 3*128*40 + 64*136) * 2;  // 82944
    const int triSmem  = 3 * 2 * 128*40 * 2;                 // 61440
    const int outSmem  = (128*136 + 128*40) * 2;             // 45056
    cudaFuncSetAttribute(proj_kernel, cudaFuncAttributeMaxDynamicSharedMemorySize, projSmem);
    cudaFuncSetAttribute(tri_kernel,  cudaFuncAttributeMaxDynamicSharedMemorySize, triSmem);
    cudaFuncSetAttribute(out_kernel,  cudaFuncAttributeMaxDynamicSharedMemorySize, outSmem);

    prep_w<<<320, 256>>>(w_g, w_ab_p, w_ab_g);
    proj_kernel<<<NP/128, 256, projSmem>>>(z, ln_in_w, ln_in_b, mask, b_ab_p, b_ab_g, out_g);
    tri_kernel<<<dim3(16, 128), 256, triSmem>>>();
    out_kernel<<<NP/128, 256, outSmem>>>(ln_out_w, ln_out_b, w_z, out_x);
}